// round 3
// baseline (speedup 1.0000x reference)
#include <cuda_runtime.h>

#define BG 128
#define NN 128
#define MM 16
#define KK 8
#define HM 16
#define DP 64
#define NE 262144
#define NSUM (BG*NN)   // 16384

// ---------------- scratch (static device globals; no runtime alloc) --------
__device__ float g_hbn[NSUM*256];    // [node][m*16+ch]   16 MB
__device__ float g_h1 [NSUM*1024];   // [node][m*64+d]    64 MB
__device__ int   g_cnt [NSUM];
__device__ int   g_off [NSUM];
__device__ int   g_cur [NSUM];
__device__ int   g_srcs[NE];

// ================= Kernel A: poly filter + MLP + BatchNorm + ReLU =========
// 1 block per graph, 512 threads. lap in smem (stride 132 to kill conflicts),
// w double-buffered in smem stored [m][n] with stride 129 (conflict-free).
// Thread t handles column m = t&15 and rows n0..n0+3 (n0 = (t>>4)*4), and
// keeps the h accumulator [4][16] in registers across all k.
__global__ __launch_bounds__(512) void kA(
    const float* __restrict__ lap, const float* __restrict__ W0,
    const float* __restrict__ mlpW, const float* __restrict__ mlpb,
    const float* __restrict__ bng,  const float* __restrict__ bnb)
{
    extern __shared__ float sm[];
    float* lap_s = sm;                    // 128*132 = 16896
    float* w_s   = lap_s + 128*132;       // 2*2064  = 4128
    float* mw_s  = w_s + 2*2064;          // 128
    float* redS  = mw_s + 128;            // 256
    float* redQ  = redS + 256;            // 256
    float* a_s   = redQ + 256;            // 16
    float* c_s   = a_s + 16;              // 16

    const int b = blockIdx.x, tid = threadIdx.x;
    const float* lb = lap + (size_t)b*NN*NN;
    for (int q = tid; q < NN*NN/4; q += 512) {
        int n = q >> 5, j4 = (q & 31) << 2;
        *(float4*)(lap_s + n*132 + j4) = *(const float4*)(lb + n*NN + j4);
    }
    if (tid < KK*HM) mw_s[tid] = mlpW[tid];

    const int m = tid & 15, g = tid >> 4, n0 = g << 2;

    float hacc[4][16];
    #pragma unroll
    for (int r = 0; r < 4; r++)
        #pragma unroll
        for (int c = 0; c < 16; c++) hacc[r][c] = 0.f;

    float wv[4];
    #pragma unroll
    for (int r = 0; r < 4; r++) {
        wv[r] = W0[(size_t)b*NN*MM + (n0+r)*MM + m];
        w_s[m*129 + n0 + r] = wv[r];
    }
    __syncthreads();
    #pragma unroll
    for (int r = 0; r < 4; r++)
        #pragma unroll
        for (int c = 0; c < 16; c++) hacc[r][c] += wv[r]*mw_s[c];

    int cur = 0;
    for (int k = 1; k < KK; k++) {
        float acc0=0.f, acc1=0.f, acc2=0.f, acc3=0.f;
        const float* wr = w_s + cur*2064 + m*129;
        const float* l0 = lap_s + (n0+0)*132;
        const float* l1 = lap_s + (n0+1)*132;
        const float* l2 = lap_s + (n0+2)*132;
        const float* l3 = lap_s + (n0+3)*132;
        #pragma unroll 8
        for (int j = 0; j < NN; j += 4) {
            float w0=wr[j], w1=wr[j+1], w2=wr[j+2], w3=wr[j+3];
            float4 a  = *(const float4*)(l0+j);
            float4 b4 = *(const float4*)(l1+j);
            float4 c4 = *(const float4*)(l2+j);
            float4 d4 = *(const float4*)(l3+j);
            acc0 += a.x *w0 + a.y *w1 + a.z *w2 + a.w *w3;
            acc1 += b4.x*w0 + b4.y*w1 + b4.z*w2 + b4.w*w3;
            acc2 += c4.x*w0 + c4.y*w1 + c4.z*w2 + c4.w*w3;
            acc3 += d4.x*w0 + d4.y*w1 + d4.z*w2 + d4.w*w3;
        }
        float* wn = w_s + (cur^1)*2064 + m*129;
        wn[n0]=acc0; wn[n0+1]=acc1; wn[n0+2]=acc2; wn[n0+3]=acc3;
        const float* mw = mw_s + k*16;
        float av[4] = {acc0, acc1, acc2, acc3};
        #pragma unroll
        for (int r = 0; r < 4; r++)
            #pragma unroll
            for (int c = 0; c < 16; c++) hacc[r][c] += av[r]*mw[c];
        __syncthreads();
        cur ^= 1;
    }
    // + mlp bias
    #pragma unroll
    for (int c = 0; c < 16; c++) {
        float bb = mlpb[c];
        #pragma unroll
        for (int r = 0; r < 4; r++) hacc[r][c] += bb;
    }
    // BatchNorm stats over (n,m) per channel: warp shuffle + smem reduce
    float s[16], q[16];
    #pragma unroll
    for (int c = 0; c < 16; c++) {
        s[c] = hacc[0][c]+hacc[1][c]+hacc[2][c]+hacc[3][c];
        q[c] = hacc[0][c]*hacc[0][c]+hacc[1][c]*hacc[1][c]
             + hacc[2][c]*hacc[2][c]+hacc[3][c]*hacc[3][c];
    }
    #pragma unroll
    for (int o = 16; o > 0; o >>= 1) {
        #pragma unroll
        for (int c = 0; c < 16; c++) {
            s[c] += __shfl_xor_sync(0xffffffffu, s[c], o);
            q[c] += __shfl_xor_sync(0xffffffffu, q[c], o);
        }
    }
    const int warp = tid >> 5, lane = tid & 31;
    if (lane == 0) {
        #pragma unroll
        for (int c = 0; c < 16; c++) { redS[warp*16+c]=s[c]; redQ[warp*16+c]=q[c]; }
    }
    __syncthreads();
    if (tid < 16) {
        float S=0.f, Q=0.f;
        #pragma unroll
        for (int w = 0; w < 16; w++) { S += redS[w*16+tid]; Q += redQ[w*16+tid]; }
        float mean = S * (1.0f/2048.0f);
        float var  = Q * (1.0f/2048.0f) - mean*mean;
        float rstd = rsqrtf(var + 1e-5f);
        float gch  = bng[tid];
        a_s[tid] = rstd * gch;
        c_s[tid] = bnb[tid] - mean * rstd * gch;
    }
    __syncthreads();
    #pragma unroll
    for (int r = 0; r < 4; r++) {
        float tmp[16];
        #pragma unroll
        for (int c = 0; c < 16; c++)
            tmp[c] = fmaxf(hacc[r][c]*a_s[c] + c_s[c], 0.f);
        float* dst = g_hbn + ((size_t)(b*NN + n0 + r))*256 + m*16;
        *(float4*)(dst+ 0) = make_float4(tmp[0], tmp[1], tmp[2], tmp[3]);
        *(float4*)(dst+ 4) = make_float4(tmp[4], tmp[5], tmp[6], tmp[7]);
        *(float4*)(dst+ 8) = make_float4(tmp[8], tmp[9], tmp[10],tmp[11]);
        *(float4*)(dst+12) = make_float4(tmp[12],tmp[13],tmp[14],tmp[15]);
    }
}

// ================= CSR build (counting sort by dst) ========================
__global__ void kZero() {
    int i = blockIdx.x*blockDim.x + threadIdx.x;
    if (i < NSUM) g_cnt[i] = 0;
}
__global__ void kCount(const int* __restrict__ ei) {
    int i = blockIdx.x*blockDim.x + threadIdx.x;
    if (i < NE) atomicAdd(&g_cnt[ei[NE + i]], 1);
}
__global__ __launch_bounds__(1024) void kScan() {
    __shared__ int ps[1024];
    const int t = threadIdx.x, base = t*16;
    int loc[16]; int s = 0;
    #pragma unroll
    for (int i = 0; i < 16; i++) { loc[i] = g_cnt[base+i]; s += loc[i]; }
    ps[t] = s; __syncthreads();
    for (int off = 1; off < 1024; off <<= 1) {
        int v = (t >= off) ? ps[t-off] : 0;
        __syncthreads();
        ps[t] += v;
        __syncthreads();
    }
    int run = ps[t] - s;   // exclusive prefix
    #pragma unroll
    for (int i = 0; i < 16; i++) { g_off[base+i]=run; g_cur[base+i]=run; run += loc[i]; }
}
__global__ void kFill(const int* __restrict__ ei) {
    int i = blockIdx.x*blockDim.x + threadIdx.x;
    if (i < NE) {
        int src = ei[i], dst = ei[NE + i];
        int p = atomicAdd(&g_cur[dst], 1);
        g_srcs[p] = src;
    }
}

// ================= Kernel C: GIN layer 1 (agg + 2 linears, fused) ==========
// 4 nodes/block, 128 threads/node. z:[16,16] -> relu(@W1a[16,64]) -> relu(@W1b[64,64])
__global__ __launch_bounds__(512) void kGin1(
    const float* __restrict__ eps1p,
    const float* __restrict__ W1a, const float* __restrict__ b1a,
    const float* __restrict__ W1b, const float* __restrict__ b1b)
{
    __shared__ float Wa_s[16*64];
    __shared__ float Wb_s[64*64];
    __shared__ float ba_s[64], bb_s[64];
    __shared__ float z_s[4][256];
    __shared__ float t_s[4][1024];
    const int tid = threadIdx.x;
    for (int i = tid; i < 16*64; i += 512) Wa_s[i] = W1a[i];
    for (int i = tid; i < 64*64; i += 512) Wb_s[i] = W1b[i];
    if (tid < 64) { ba_s[tid] = b1a[tid]; bb_s[tid] = b1b[tid]; }

    const int g = tid >> 7, lt = tid & 127;
    const int v = blockIdx.x*4 + g;
    const float eps = 1.0f + eps1p[0];

    float a0 = 0.f, a1 = 0.f;
    const int beg = g_off[v], cnt = g_cnt[v];
    for (int e = 0; e < cnt; e++) {
        const float* hr = g_hbn + (size_t)g_srcs[beg+e]*256;
        a0 += hr[lt]; a1 += hr[128+lt];
    }
    const float* hv = g_hbn + (size_t)v*256;
    z_s[g][lt]     = eps*hv[lt]     + a0;
    z_s[g][128+lt] = eps*hv[128+lt] + a1;
    __syncthreads();

    const int dq = lt & 15, mg = lt >> 4;
    const int m0 = mg*2, m1 = m0+1;
    {   // GEMM1: [16,16] @ [16,64]
        float4 bias = *(const float4*)(ba_s + dq*4);
        float4 A = bias, B = bias;
        #pragma unroll
        for (int c = 0; c < 16; c++) {
            float4 w = *(const float4*)(Wa_s + c*64 + dq*4);
            float z0 = z_s[g][m0*16+c], z1 = z_s[g][m1*16+c];
            A.x += z0*w.x; A.y += z0*w.y; A.z += z0*w.z; A.w += z0*w.w;
            B.x += z1*w.x; B.y += z1*w.y; B.z += z1*w.z; B.w += z1*w.w;
        }
        A.x=fmaxf(A.x,0.f); A.y=fmaxf(A.y,0.f); A.z=fmaxf(A.z,0.f); A.w=fmaxf(A.w,0.f);
        B.x=fmaxf(B.x,0.f); B.y=fmaxf(B.y,0.f); B.z=fmaxf(B.z,0.f); B.w=fmaxf(B.w,0.f);
        *(float4*)(&t_s[g][m0*64 + dq*4]) = A;
        *(float4*)(&t_s[g][m1*64 + dq*4]) = B;
    }
    __syncthreads();
    {   // GEMM2: [16,64] @ [64,64] -> h1
        float4 bias = *(const float4*)(bb_s + dq*4);
        float4 A = bias, B = bias;
        #pragma unroll
        for (int c = 0; c < 64; c++) {
            float4 w = *(const float4*)(Wb_s + c*64 + dq*4);
            float t0 = t_s[g][m0*64+c], t1 = t_s[g][m1*64+c];
            A.x += t0*w.x; A.y += t0*w.y; A.z += t0*w.z; A.w += t0*w.w;
            B.x += t1*w.x; B.y += t1*w.y; B.z += t1*w.z; B.w += t1*w.w;
        }
        A.x=fmaxf(A.x,0.f); A.y=fmaxf(A.y,0.f); A.z=fmaxf(A.z,0.f); A.w=fmaxf(A.w,0.f);
        B.x=fmaxf(B.x,0.f); B.y=fmaxf(B.y,0.f); B.z=fmaxf(B.z,0.f); B.w=fmaxf(B.w,0.f);
        float* o = g_h1 + (size_t)v*1024;
        *(float4*)(o + m0*64 + dq*4) = A;
        *(float4*)(o + m1*64 + dq*4) = B;
    }
}

// ================= Kernel D: GIN layer 2 + sample-sum ======================
// 4 nodes/block, 128 threads/node. Dominant kernel: 1.07 GB L2-resident gather.
__global__ __launch_bounds__(512) void kGin2(
    const float* __restrict__ eps2p,
    const float* __restrict__ W2a, const float* __restrict__ b2a,
    const float* __restrict__ W2b, const float* __restrict__ b2b,
    float* __restrict__ out)
{
    extern __shared__ float sd[];
    float* Wa_s = sd;              // 4096
    float* Wb_s = Wa_s + 4096;     // 4096
    float* ba_s = Wb_s + 4096;     // 64
    float* bb_s = ba_s + 64;       // 64
    float* z_a  = bb_s + 64;       // 4*1024 (reused as m-reduction buffer)
    float* t_a  = z_a + 4096;      // 4*1024
    const int tid = threadIdx.x;
    for (int i = tid; i < 4096; i += 512) { Wa_s[i] = W2a[i]; Wb_s[i] = W2b[i]; }
    if (tid < 64) { ba_s[tid] = b2a[tid]; bb_s[tid] = b2b[tid]; }

    const int g = tid >> 7, lt = tid & 127;
    const int v = blockIdx.x*4 + g;
    float* zg = z_a + g*1024;
    float* tg = t_a + g*1024;
    const float eps = 1.0f + eps2p[0];

    float4 a0 = make_float4(0.f,0.f,0.f,0.f), a1 = a0;
    const int beg = g_off[v], cnt = g_cnt[v];
    for (int e = 0; e < cnt; e++) {
        const float4* p = (const float4*)(g_h1 + (size_t)g_srcs[beg+e]*1024 + lt*8);
        float4 x = p[0], y = p[1];
        a0.x += x.x; a0.y += x.y; a0.z += x.z; a0.w += x.w;
        a1.x += y.x; a1.y += y.y; a1.z += y.z; a1.w += y.w;
    }
    const float4* hv = (const float4*)(g_h1 + (size_t)v*1024 + lt*8);
    float4 h0 = hv[0], h1 = hv[1], z0, z1;
    z0.x = eps*h0.x + a0.x; z0.y = eps*h0.y + a0.y;
    z0.z = eps*h0.z + a0.z; z0.w = eps*h0.w + a0.w;
    z1.x = eps*h1.x + a1.x; z1.y = eps*h1.y + a1.y;
    z1.z = eps*h1.z + a1.z; z1.w = eps*h1.w + a1.w;
    *(float4*)(zg + lt*8)     = z0;
    *(float4*)(zg + lt*8 + 4) = z1;
    __syncthreads();

    const int dq = lt & 15, mg = lt >> 4;
    const int m0 = mg*2, m1 = m0+1;
    {   // GEMM1: [16,64] @ [64,64] -> t (relu)
        float4 bias = *(const float4*)(ba_s + dq*4);
        float4 A = bias, B = bias;
        #pragma unroll
        for (int c = 0; c < 64; c++) {
            float4 w = *(const float4*)(Wa_s + c*64 + dq*4);
            float x0 = zg[m0*64+c], x1 = zg[m1*64+c];
            A.x += x0*w.x; A.y += x0*w.y; A.z += x0*w.z; A.w += x0*w.w;
            B.x += x1*w.x; B.y += x1*w.y; B.z += x1*w.z; B.w += x1*w.w;
        }
        A.x=fmaxf(A.x,0.f); A.y=fmaxf(A.y,0.f); A.z=fmaxf(A.z,0.f); A.w=fmaxf(A.w,0.f);
        B.x=fmaxf(B.x,0.f); B.y=fmaxf(B.y,0.f); B.z=fmaxf(B.z,0.f); B.w=fmaxf(B.w,0.f);
        *(float4*)(tg + m0*64 + dq*4) = A;
        *(float4*)(tg + m1*64 + dq*4) = B;
    }
    __syncthreads();
    {   // GEMM2: [16,64] @ [64,64], relu, partial sum over this thread's 2 m
        float4 bias = *(const float4*)(bb_s + dq*4);
        float4 A = bias, B = bias;
        #pragma unroll
        for (int c = 0; c < 64; c++) {
            float4 w = *(const float4*)(Wb_s + c*64 + dq*4);
            float x0 = tg[m0*64+c], x1 = tg[m1*64+c];
            A.x += x0*w.x; A.y += x0*w.y; A.z += x0*w.z; A.w += x0*w.w;
            B.x += x1*w.x; B.y += x1*w.y; B.z += x1*w.z; B.w += x1*w.w;
        }
        float4 P;
        P.x = fmaxf(A.x,0.f)+fmaxf(B.x,0.f);
        P.y = fmaxf(A.y,0.f)+fmaxf(B.y,0.f);
        P.z = fmaxf(A.z,0.f)+fmaxf(B.z,0.f);
        P.w = fmaxf(A.w,0.f)+fmaxf(B.w,0.f);
        *(float4*)(zg + mg*64 + dq*4) = P;   // zg dead -> reuse as reduce buf
    }
    __syncthreads();
    if (lt < 64) {
        float ssum = 0.f;
        #pragma unroll
        for (int r = 0; r < 8; r++) ssum += zg[r*64 + lt];
        out[(size_t)v*64 + lt] = ssum;
    }
}

// ================= launch ==================================================
extern "C" void kernel_launch(void* const* d_in, const int* in_sizes, int n_in,
                              void* d_out, int out_size)
{
    const float* lap  = (const float*)d_in[0];
    const float* W0   = (const float*)d_in[1];
    const float* mlpW = (const float*)d_in[2];
    const float* mlpb = (const float*)d_in[3];
    const float* bng  = (const float*)d_in[4];
    const float* bnb  = (const float*)d_in[5];
    const float* eps1 = (const float*)d_in[6];
    const float* W1a  = (const float*)d_in[7];
    const float* b1a  = (const float*)d_in[8];
    const float* W1b  = (const float*)d_in[9];
    const float* b1b  = (const float*)d_in[10];
    const float* eps2 = (const float*)d_in[11];
    const float* W2a  = (const float*)d_in[12];
    const float* b2a  = (const float*)d_in[13];
    const float* W2b  = (const float*)d_in[14];
    const float* b2b  = (const float*)d_in[15];
    const int*   ei   = (const int*)d_in[16];
    float* out = (float*)d_out;

    const int SMEM_A = 21696 * 4;   // 86784 B
    const int SMEM_D = 16512 * 4;   // 66048 B
    cudaFuncSetAttribute(kA,    cudaFuncAttributeMaxDynamicSharedMemorySize, SMEM_A);
    cudaFuncSetAttribute(kGin2, cudaFuncAttributeMaxDynamicSharedMemorySize, SMEM_D);

    kA   <<<BG, 512, SMEM_A>>>(lap, W0, mlpW, mlpb, bng, bnb);
    kZero<<<NSUM/256, 256>>>();
    kCount<<<NE/256, 256>>>(ei);
    kScan<<<1, 1024>>>();
    kFill<<<NE/256, 256>>>(ei);
    kGin1<<<NSUM/4, 512>>>(eps1, W1a, b1a, W1b, b1b);
    kGin2<<<NSUM/4, 512, SMEM_D>>>(eps2, W2a, b2a, W2b, b2b, out);
}